// round 2
// baseline (speedup 1.0000x reference)
#include <cuda_runtime.h>
#include <cstdint>
#include <math.h>

#define NTOK 8192
#define DDIM 512
#define FDIM 2048
#define GDIM 102
#define GAMMA_C 0.5f
#define NEG_C -1e9f
#define SCALE_C 0.044194173824159216f  /* 1/sqrt(512) */

#define TILE 128
#define BK 8

// ---------------- scratch (static device allocations; no cudaMalloc) -------
__device__ float g_dropx[NTOK * DDIM];
__device__ float g_Qr[NTOK * DDIM];
__device__ float g_Kr[NTOK * DDIM];
__device__ float g_Qf[NTOK * DDIM];
__device__ float g_Kf[NTOK * DDIM];
__device__ float g_V[NTOK * DDIM];
__device__ float g_Sr[(size_t)NTOK * NTOK];
__device__ float g_Sf[(size_t)NTOK * NTOK];
__device__ float g_attnout[NTOK * DDIM];
__device__ float g_h1[NTOK * DDIM];
__device__ float g_ffmid[NTOK * FDIM];
__device__ float g_h2[NTOK * DDIM];
__device__ float g_recon[NTOK * DDIM];
__device__ float g_head[NTOK * DDIM];

// ---------------- small helpers --------------------------------------------
__device__ __forceinline__ float warpSum(float v) {
#pragma unroll
    for (int o = 16; o > 0; o >>= 1) v += __shfl_xor_sync(0xFFFFFFFFu, v, o);
    return v;
}
__device__ __forceinline__ float warpMax(float v) {
#pragma unroll
    for (int o = 16; o > 0; o >>= 1) v = fmaxf(v, __shfl_xor_sync(0xFFFFFFFFu, v, o));
    return v;
}

// ---------------- elementwise kernels --------------------------------------
__global__ void copy4_kernel(const float4* __restrict__ src, float4* __restrict__ dst, int n4) {
    int i = blockIdx.x * blockDim.x + threadIdx.x;
    if (i < n4) dst[i] = src[i];
}

__global__ void scatter_zero_kernel(const int* __restrict__ drop_idx, float* __restrict__ dropx) {
    int idx = blockIdx.x * blockDim.x + threadIdx.x;
    if (idx >= NTOK * GDIM) return;
    int row = idx / GDIM;
    int c = drop_idx[idx];
    dropx[(size_t)row * DDIM + c] = 0.0f;
}

__global__ void gather_out_kernel(const float* __restrict__ x, const float* __restrict__ h,
                                  const int* __restrict__ drop_idx, float* __restrict__ out) {
    int idx = blockIdx.x * blockDim.x + threadIdx.x;
    if (idx >= NTOK * GDIM) return;
    int row = idx / GDIM;
    int c = drop_idx[idx];
    out[idx] = x[(size_t)row * DDIM + c];
    out[(size_t)NTOK * GDIM + idx] = h[(size_t)row * DDIM + c];
}

// ---------------- GEMM: C = act(A[M,K] @ B[K,Nc] + bias) --------------------
// classic 128x128x8 SIMT tile, 256 threads, 8x8 per thread (4+4 split frags)
template <int ACT>  // 0 = none, 1 = exact gelu
__global__ void __launch_bounds__(256) gemm_nn_kernel(
    const float* __restrict__ A, const float* __restrict__ B,
    const float* __restrict__ bias, float* __restrict__ C,
    int M, int Nc, int K) {
    __shared__ float As[BK][TILE];
    __shared__ float Bs[BK][TILE];
    const int tid = threadIdx.x;
    const int tx = tid & 15;
    const int ty = tid >> 4;
    const int row_base = blockIdx.y * TILE;
    const int col_base = blockIdx.x * TILE;

    float acc[8][8];
#pragma unroll
    for (int i = 0; i < 8; i++)
#pragma unroll
        for (int j = 0; j < 8; j++) acc[i][j] = 0.0f;

    const int am = tid >> 1;          // 0..127 (row within A tile)
    const int ak = (tid & 1) * 4;     // 0 or 4
    const int bk = tid >> 5;          // 0..7
    const int bn = (tid & 31) * 4;    // 0..124

    const float* Aptr = A + (size_t)(row_base + am) * K + ak;

    for (int k0 = 0; k0 < K; k0 += BK) {
        float4 av = *(const float4*)(Aptr + k0);
        float4 bv = *(const float4*)(B + (size_t)(k0 + bk) * Nc + col_base + bn);
        As[ak + 0][am] = av.x; As[ak + 1][am] = av.y;
        As[ak + 2][am] = av.z; As[ak + 3][am] = av.w;
        *(float4*)&Bs[bk][bn] = bv;
        __syncthreads();
#pragma unroll
        for (int k = 0; k < BK; k++) {
            float a[8], b[8];
#pragma unroll
            for (int i = 0; i < 4; i++) {
                a[i]     = As[k][ty * 4 + i];
                a[4 + i] = As[k][64 + ty * 4 + i];
                b[i]     = Bs[k][tx * 4 + i];
                b[4 + i] = Bs[k][64 + tx * 4 + i];
            }
#pragma unroll
            for (int i = 0; i < 8; i++)
#pragma unroll
                for (int j = 0; j < 8; j++) acc[i][j] += a[i] * b[j];
        }
        __syncthreads();
    }

#pragma unroll
    for (int i = 0; i < 8; i++) {
        int r = row_base + ((i < 4) ? (ty * 4 + i) : (64 + ty * 4 + (i - 4)));
#pragma unroll
        for (int j = 0; j < 8; j++) {
            int c = col_base + ((j < 4) ? (tx * 4 + j) : (64 + tx * 4 + (j - 4)));
            float v = acc[i][j];
            if (bias) v += bias[c];
            if (ACT == 1) v = 0.5f * v * (1.0f + erff(v * 0.70710678118654752f));
            C[(size_t)r * Nc + c] = v;
        }
    }
}

// ---------------- NT GEMM with mask epilogue: S = masked(A @ B^T * scale) ---
// mask is int32 (harness widens jax bool to int32): nonzero = masked
__global__ void __launch_bounds__(256) gemm_nt_mask_kernel(
    const float* __restrict__ A, const float* __restrict__ B,
    const int* __restrict__ mask, float* __restrict__ S,
    int Nn, int K, float scale) {
    __shared__ float As[BK][TILE];
    __shared__ float Bs[BK][TILE];
    const int tid = threadIdx.x;
    const int tx = tid & 15;
    const int ty = tid >> 4;
    const int row_base = blockIdx.y * TILE;
    const int col_base = blockIdx.x * TILE;

    float acc[8][8];
#pragma unroll
    for (int i = 0; i < 8; i++)
#pragma unroll
        for (int j = 0; j < 8; j++) acc[i][j] = 0.0f;

    const int am = tid >> 1;
    const int ak = (tid & 1) * 4;
    const float* Aptr = A + (size_t)(row_base + am) * K + ak;
    const float* Bptr = B + (size_t)(col_base + am) * K + ak;

    for (int k0 = 0; k0 < K; k0 += BK) {
        float4 av = *(const float4*)(Aptr + k0);
        float4 bv = *(const float4*)(Bptr + k0);
        As[ak + 0][am] = av.x; As[ak + 1][am] = av.y;
        As[ak + 2][am] = av.z; As[ak + 3][am] = av.w;
        Bs[ak + 0][am] = bv.x; Bs[ak + 1][am] = bv.y;
        Bs[ak + 2][am] = bv.z; Bs[ak + 3][am] = bv.w;
        __syncthreads();
#pragma unroll
        for (int k = 0; k < BK; k++) {
            float a[8], b[8];
#pragma unroll
            for (int i = 0; i < 4; i++) {
                a[i]     = As[k][ty * 4 + i];
                a[4 + i] = As[k][64 + ty * 4 + i];
                b[i]     = Bs[k][tx * 4 + i];
                b[4 + i] = Bs[k][64 + tx * 4 + i];
            }
#pragma unroll
            for (int i = 0; i < 8; i++)
#pragma unroll
                for (int j = 0; j < 8; j++) acc[i][j] += a[i] * b[j];
        }
        __syncthreads();
    }

#pragma unroll
    for (int i = 0; i < 8; i++) {
        int r = row_base + ((i < 4) ? (ty * 4 + i) : (64 + ty * 4 + (i - 4)));
#pragma unroll
        for (int j = 0; j < 8; j++) {
            int c = col_base + ((j < 4) ? (tx * 4 + j) : (64 + tx * 4 + (j - 4)));
            size_t idx = (size_t)r * Nn + c;
            S[idx] = mask[idx] ? NEG_C : acc[i][j] * scale;
        }
    }
}

// ---------------- dual-mask softmax combine (one block per row) -------------
// attn[j] = (exp(sr-m) + GAMMA*exp(sf-m)) / sum(...)   ((1+GAMMA) cancels)
__global__ void softmax_combine_kernel(const float* __restrict__ Sr,
                                       const float* __restrict__ Sf,
                                       float* __restrict__ attn) {
    extern __shared__ float sm[];
    float* s_r = sm;
    float* s_f = sm + NTOK;
    __shared__ float red[8];
    const int row = blockIdx.x;
    const int tid = threadIdx.x;
    const int lane = tid & 31, wid = tid >> 5;
    const float* Rr = Sr + (size_t)row * NTOK;
    const float* Rf = Sf + (size_t)row * NTOK;

    float m = -3.4e38f;
    for (int j = tid; j < NTOK; j += 256) {
        float a = Rr[j], b = Rf[j];
        s_r[j] = a; s_f[j] = b;
        m = fmaxf(m, fmaxf(a, b));
    }
    m = warpMax(m);
    if (lane == 0) red[wid] = m;
    __syncthreads();
    if (wid == 0) {
        float t = (lane < 8) ? red[lane] : -3.4e38f;
        t = warpMax(t);
        if (lane == 0) red[0] = t;
    }
    __syncthreads();
    m = red[0];
    __syncthreads();

    float sum = 0.0f;
    for (int j = tid; j < NTOK; j += 256) {
        float e = __expf(s_r[j] - m) + GAMMA_C * __expf(s_f[j] - m);
        s_r[j] = e;
        sum += e;
    }
    sum = warpSum(sum);
    if (lane == 0) red[wid] = sum;
    __syncthreads();
    if (wid == 0) {
        float t = (lane < 8) ? red[lane] : 0.0f;
        t = warpSum(t);
        if (lane == 0) red[0] = t;
    }
    __syncthreads();
    float inv = 1.0f / red[0];

    float* Ao = attn + (size_t)row * NTOK;
    for (int j = tid; j < NTOK; j += 256) Ao[j] = s_r[j] * inv;
}

// ---------------- residual + layernorm (one block per row, 256 thr) ---------
__global__ void add_ln_kernel(const float* __restrict__ a, const float* __restrict__ b,
                              const float* __restrict__ gamma, const float* __restrict__ beta,
                              float* __restrict__ out) {
    __shared__ float red[8];
    const int row = blockIdx.x;
    const int tid = threadIdx.x;
    const int lane = tid & 31, wid = tid >> 5;
    const float* ar = a + (size_t)row * DDIM;
    const float* br = b + (size_t)row * DDIM;
    float v0 = ar[tid] + br[tid];
    float v1 = ar[tid + 256] + br[tid + 256];

    float s = warpSum(v0 + v1);
    if (lane == 0) red[wid] = s;
    __syncthreads();
    if (wid == 0) {
        float t = (lane < 8) ? red[lane] : 0.0f;
        t = warpSum(t);
        if (lane == 0) red[0] = t;
    }
    __syncthreads();
    float mu = red[0] * (1.0f / DDIM);
    __syncthreads();

    float d0 = v0 - mu, d1 = v1 - mu;
    float q = warpSum(d0 * d0 + d1 * d1);
    if (lane == 0) red[wid] = q;
    __syncthreads();
    if (wid == 0) {
        float t = (lane < 8) ? red[lane] : 0.0f;
        t = warpSum(t);
        if (lane == 0) red[0] = t;
    }
    __syncthreads();
    float rstd = rsqrtf(red[0] * (1.0f / DDIM) + 1e-5f);

    float* orow = out + (size_t)row * DDIM;
    orow[tid]       = d0 * rstd * gamma[tid]       + beta[tid];
    orow[tid + 256] = d1 * rstd * gamma[tid + 256] + beta[tid + 256];
}

// ---------------- host orchestration ----------------------------------------
static void run_attention(const float* h, const float* Wq_r, const float* Wk_r,
                          const float* Wq_f, const float* Wk_f, const float* Wv,
                          const int* rmask, const int* fmask,
                          float* Qr, float* Kr, float* Qf, float* Kf, float* V,
                          float* Sr, float* Sf, float* attnout) {
    dim3 gP(DDIM / TILE, NTOK / TILE);
    gemm_nn_kernel<0><<<gP, 256>>>(h, Wq_r, nullptr, Qr, NTOK, DDIM, DDIM);
    gemm_nn_kernel<0><<<gP, 256>>>(h, Wk_r, nullptr, Kr, NTOK, DDIM, DDIM);
    gemm_nn_kernel<0><<<gP, 256>>>(h, Wq_f, nullptr, Qf, NTOK, DDIM, DDIM);
    gemm_nn_kernel<0><<<gP, 256>>>(h, Wk_f, nullptr, Kf, NTOK, DDIM, DDIM);
    gemm_nn_kernel<0><<<gP, 256>>>(h, Wv, nullptr, V, NTOK, DDIM, DDIM);
    dim3 gS(NTOK / TILE, NTOK / TILE);
    gemm_nt_mask_kernel<<<gS, 256>>>(Qr, Kr, rmask, Sr, NTOK, DDIM, SCALE_C);
    gemm_nt_mask_kernel<<<gS, 256>>>(Qf, Kf, fmask, Sf, NTOK, DDIM, SCALE_C);
    softmax_combine_kernel<<<NTOK, 256, 2 * NTOK * sizeof(float)>>>(Sr, Sf, Sr);
    gemm_nn_kernel<0><<<gP, 256>>>(Sr, V, nullptr, attnout, NTOK, DDIM, NTOK);
}

extern "C" void kernel_launch(void* const* d_in, const int* in_sizes, int n_in,
                              void* d_out, int out_size) {
    const float* x        = (const float*)d_in[0];
    const int* drop_idx   = (const int*)d_in[1];
    const int* rmask      = (const int*)d_in[2];
    const int* fmask      = (const int*)d_in[3];
    const float* enc_Wq_r = (const float*)d_in[4];
    const float* enc_Wk_r = (const float*)d_in[5];
    const float* enc_Wq_f = (const float*)d_in[6];
    const float* enc_Wk_f = (const float*)d_in[7];
    const float* enc_Wv   = (const float*)d_in[8];
    const float* dec_Wq_r = (const float*)d_in[9];
    const float* dec_Wk_r = (const float*)d_in[10];
    const float* dec_Wq_f = (const float*)d_in[11];
    const float* dec_Wk_f = (const float*)d_in[12];
    const float* dec_Wv   = (const float*)d_in[13];
    const float* ff_W1    = (const float*)d_in[14];
    const float* ff_b1    = (const float*)d_in[15];
    const float* ff_W2    = (const float*)d_in[16];
    const float* ff_b2    = (const float*)d_in[17];
    const float* ln1_g    = (const float*)d_in[18];
    const float* ln1_b    = (const float*)d_in[19];
    const float* ln2_g    = (const float*)d_in[20];
    const float* ln2_b    = (const float*)d_in[21];
    const float* ln3_g    = (const float*)d_in[22];
    const float* ln3_b    = (const float*)d_in[23];
    const float* head_W   = (const float*)d_in[24];
    const float* head_b   = (const float*)d_in[25];
    float* out = (float*)d_out;

    float *dropx, *Qr, *Kr, *Qf, *Kf, *V, *Sr, *Sf, *attnout, *h1, *ffmid, *h2, *recon, *head;
    cudaGetSymbolAddress((void**)&dropx, g_dropx);
    cudaGetSymbolAddress((void**)&Qr, g_Qr);
    cudaGetSymbolAddress((void**)&Kr, g_Kr);
    cudaGetSymbolAddress((void**)&Qf, g_Qf);
    cudaGetSymbolAddress((void**)&Kf, g_Kf);
    cudaGetSymbolAddress((void**)&V, g_V);
    cudaGetSymbolAddress((void**)&Sr, g_Sr);
    cudaGetSymbolAddress((void**)&Sf, g_Sf);
    cudaGetSymbolAddress((void**)&attnout, g_attnout);
    cudaGetSymbolAddress((void**)&h1, g_h1);
    cudaGetSymbolAddress((void**)&ffmid, g_ffmid);
    cudaGetSymbolAddress((void**)&h2, g_h2);
    cudaGetSymbolAddress((void**)&recon, g_recon);
    cudaGetSymbolAddress((void**)&head, g_head);

    // softmax needs 64KB dynamic smem (non-stream API; safe under capture)
    cudaFuncSetAttribute(softmax_combine_kernel,
                         cudaFuncAttributeMaxDynamicSharedMemorySize,
                         2 * NTOK * (int)sizeof(float));

    // 1) drop_x
    int n4 = NTOK * DDIM / 4;
    copy4_kernel<<<(n4 + 255) / 256, 256>>>((const float4*)x, (float4*)dropx, n4);
    scatter_zero_kernel<<<(NTOK * GDIM + 255) / 256, 256>>>(drop_idx, dropx);

    // 2) encoder attention + residual LN1
    run_attention(dropx, enc_Wq_r, enc_Wk_r, enc_Wq_f, enc_Wk_f, enc_Wv,
                  rmask, fmask, Qr, Kr, Qf, Kf, V, Sr, Sf, attnout);
    add_ln_kernel<<<NTOK, 256>>>(attnout, dropx, ln1_g, ln1_b, h1);

    // 3) FF block + residual LN2
    gemm_nn_kernel<1><<<dim3(FDIM / TILE, NTOK / TILE), 256>>>(h1, ff_W1, ff_b1, ffmid, NTOK, FDIM, DDIM);
    gemm_nn_kernel<0><<<dim3(DDIM / TILE, NTOK / TILE), 256>>>(ffmid, ff_W2, ff_b2, attnout, NTOK, DDIM, FDIM);
    add_ln_kernel<<<NTOK, 256>>>(attnout, h1, ln2_g, ln2_b, h2);

    // 4) decoder attention + residual LN3
    run_attention(h2, dec_Wq_r, dec_Wk_r, dec_Wq_f, dec_Wk_f, dec_Wv,
                  rmask, fmask, Qr, Kr, Qf, Kf, V, Sr, Sf, attnout);
    add_ln_kernel<<<NTOK, 256>>>(attnout, h2, ln3_g, ln3_b, recon);

    // 5) head + gather
    gemm_nn_kernel<0><<<dim3(DDIM / TILE, NTOK / TILE), 256>>>(recon, head_W, head_b, head, NTOK, DDIM, DDIM);
    gather_out_kernel<<<(NTOK * GDIM + 255) / 256, 256>>>(x, head, drop_idx, out);
}